// round 1
// baseline (speedup 1.0000x reference)
#include <cuda_runtime.h>
#include <math.h>

#define BS   4096
#define NSLOT 32
#define D    256

// Scratch (device globals — no runtime allocation allowed).
// Layout: [slot][batch][dim]
__device__ float g_query[(size_t)NSLOT * BS * D];
__device__ float g_keyp [(size_t)NSLOT * BS * D];
__device__ float g_value[(size_t)NSLOT * BS * D];

// ---------------------------------------------------------------------------
// Phase 1: 96 independent GEMMs  C[4096,256] = X[4096,256] @ W[256,256]
// grid = (2, 32, 96), block = 256.  Tile 128x128, K-step 16, 8x8 per thread.
// z in [0,32): query proj; [32,64): key proj; [64,96): value proj.
// ---------------------------------------------------------------------------
__global__ __launch_bounds__(256) void proj_kernel(
    const float* __restrict__ q,
    const float* __restrict__ k,
    const float* __restrict__ qw,
    const float* __restrict__ kw,
    const float* __restrict__ vw)
{
    const int z = blockIdx.z;
    const float* X;
    const float* W;
    float* C;
    if (z < 32) {
        X = q + (size_t)z * BS * D;
        W = qw + (size_t)z * D * D;
        C = g_query + (size_t)z * BS * D;
    } else if (z < 64) {
        const int s = z - 32;
        X = k + (size_t)s * BS * D;
        W = kw + (size_t)s * D * D;
        C = g_keyp + (size_t)s * BS * D;
    } else {
        const int s = z - 64;
        X = k + (size_t)s * BS * D;
        W = vw + (size_t)s * D * D;
        C = g_value + (size_t)s * BS * D;
    }

    __shared__ float As[16][128];   // [k][m]  (A stored transposed)
    __shared__ float Bs[16][128];   // [k][n]

    const int tid  = threadIdx.x;
    const int tx   = tid & 15;      // 0..15 -> n
    const int ty   = tid >> 4;      // 0..15 -> m
    const int row0 = blockIdx.y * 128;
    const int col0 = blockIdx.x * 128;

    float acc[8][8];
#pragma unroll
    for (int i = 0; i < 8; i++)
#pragma unroll
        for (int j = 0; j < 8; j++) acc[i][j] = 0.0f;

    for (int kk = 0; kk < D; kk += 16) {
        // Load A tile: 128 rows x 16 k  (float4 along k, scatter-transpose to As)
#pragma unroll
        for (int r = 0; r < 2; r++) {
            const int arow = (tid >> 2) + r * 64;
            const int ak   = (tid & 3) * 4;
            const float4 v = *(const float4*)&X[(size_t)(row0 + arow) * D + kk + ak];
            As[ak + 0][arow] = v.x;
            As[ak + 1][arow] = v.y;
            As[ak + 2][arow] = v.z;
            As[ak + 3][arow] = v.w;
        }
        // Load B tile: 16 k x 128 n (direct, float4)
#pragma unroll
        for (int r = 0; r < 2; r++) {
            const int bk = (tid >> 5) + r * 8;
            const int bn = (tid & 31) * 4;
            *(float4*)&Bs[bk][bn] =
                *(const float4*)&W[(size_t)(kk + bk) * D + col0 + bn];
        }
        __syncthreads();

#pragma unroll
        for (int k2 = 0; k2 < 16; k2++) {
            float a[8], b[8];
            *(float4*)&a[0] = *(const float4*)&As[k2][ty * 8];
            *(float4*)&a[4] = *(const float4*)&As[k2][ty * 8 + 4];
            *(float4*)&b[0] = *(const float4*)&Bs[k2][tx * 8];
            *(float4*)&b[4] = *(const float4*)&Bs[k2][tx * 8 + 4];
#pragma unroll
            for (int i = 0; i < 8; i++)
#pragma unroll
                for (int j = 0; j < 8; j++)
                    acc[i][j] = fmaf(a[i], b[j], acc[i][j]);
        }
        __syncthreads();
    }

#pragma unroll
    for (int i = 0; i < 8; i++) {
        const int row = row0 + ty * 8 + i;
#pragma unroll
        for (int j = 0; j < 8; j += 4) {
            float4 v;
            v.x = acc[i][j + 0];
            v.y = acc[i][j + 1];
            v.z = acc[i][j + 2];
            v.w = acc[i][j + 3];
            *(float4*)&C[(size_t)row * D + col0 + tx * 8 + j] = v;
        }
    }
}

// ---------------------------------------------------------------------------
// Phase 2: per-batch attention. grid = 4096, block = 256.
// smem: sq[32][256], sk[32][257] (padded), sv[32][256], lg[32][32]
// ---------------------------------------------------------------------------
#define SK_STRIDE 257
#define SMEM_FLOATS (32*256 + 32*SK_STRIDE + 32*256 + 32*32)

__global__ __launch_bounds__(256) void attn_kernel(float* __restrict__ out)
{
    extern __shared__ float sm[];
    float* sq = sm;                        // 32*256
    float* sk = sq + 32 * 256;             // 32*257
    float* sv = sk + 32 * SK_STRIDE;       // 32*256
    float* lg = sv + 32 * 256;             // 32*32

    const int b   = blockIdx.x;
    const int tid = threadIdx.x;

    // Stage q/k/v tiles for this batch element
    for (int i = tid; i < 32 * 64; i += 256) {
        const int n  = i >> 6;
        const int a4 = (i & 63) * 4;
        const size_t g = (size_t)n * BS * D + (size_t)b * D + a4;
        const float4 vq = *(const float4*)&g_query[g];
        *(float4*)&sq[n * 256 + a4] = vq;
        const float4 vv = *(const float4*)&g_value[g];
        *(float4*)&sv[n * 256 + a4] = vv;
        const float4 vk = *(const float4*)&g_keyp[g];
        sk[n * SK_STRIDE + a4 + 0] = vk.x;
        sk[n * SK_STRIDE + a4 + 1] = vk.y;
        sk[n * SK_STRIDE + a4 + 2] = vk.z;
        sk[n * SK_STRIDE + a4 + 3] = vk.w;
    }
    __syncthreads();

    // logits[n][m] = sum_a sq[n][a]*sk[m][a]; 16x16 threads, 2x2 per thread
    {
        const int ltx = tid & 15;
        const int lty = tid >> 4;
        const int n0 = lty * 2;
        const int m0 = ltx * 2;
        float c00 = 0.f, c01 = 0.f, c10 = 0.f, c11 = 0.f;
        const float* q0p = &sq[n0 * 256];
        const float* q1p = &sq[(n0 + 1) * 256];
        const float* k0p = &sk[m0 * SK_STRIDE];
        const float* k1p = &sk[(m0 + 1) * SK_STRIDE];
#pragma unroll 8
        for (int a = 0; a < 256; a++) {
            const float q0 = q0p[a];
            const float q1 = q1p[a];
            const float k0 = k0p[a];
            const float k1 = k1p[a];
            c00 = fmaf(q0, k0, c00);
            c01 = fmaf(q0, k1, c01);
            c10 = fmaf(q1, k0, c10);
            c11 = fmaf(q1, k1, c11);
        }
        lg[n0 * 32 + m0]           = c00;
        lg[n0 * 32 + m0 + 1]       = c01;
        lg[(n0 + 1) * 32 + m0]     = c10;
        lg[(n0 + 1) * 32 + m0 + 1] = c11;
    }
    __syncthreads();

    // softmax over m with temperature sqrt(256)=16 (one thread per row)
    if (tid < 32) {
        float mx = -1e30f;
#pragma unroll
        for (int m = 0; m < 32; m++) mx = fmaxf(mx, lg[tid * 32 + m]);
        float s = 0.0f;
        float e[32];
#pragma unroll
        for (int m = 0; m < 32; m++) {
            e[m] = expf((lg[tid * 32 + m] - mx) * (1.0f / 16.0f));
            s += e[m];
        }
        const float inv = 1.0f / s;
#pragma unroll
        for (int m = 0; m < 32; m++) lg[tid * 32 + m] = e[m] * inv;
    }
    __syncthreads();

    // out[n][b][o] = sum_m p[n][m] * sv[m][o]
    // thread: otx = tid%64 -> 4 contiguous o; oty = tid/64 -> 8 n rows (stride 4)
    {
        const int otx = tid & 63;
        const int oty = tid >> 6;
        float acc[8][4];
#pragma unroll
        for (int j = 0; j < 8; j++)
#pragma unroll
            for (int c = 0; c < 4; c++) acc[j][c] = 0.0f;

#pragma unroll 4
        for (int m = 0; m < 32; m++) {
            const float4 v = *(const float4*)&sv[m * 256 + otx * 4];
#pragma unroll
            for (int j = 0; j < 8; j++) {
                const float p = lg[(oty + j * 4) * 32 + m];
                acc[j][0] = fmaf(p, v.x, acc[j][0]);
                acc[j][1] = fmaf(p, v.y, acc[j][1]);
                acc[j][2] = fmaf(p, v.z, acc[j][2]);
                acc[j][3] = fmaf(p, v.w, acc[j][3]);
            }
        }
#pragma unroll
        for (int j = 0; j < 8; j++) {
            const int n = oty + j * 4;
            float4 r;
            r.x = acc[j][0]; r.y = acc[j][1]; r.z = acc[j][2]; r.w = acc[j][3];
            *(float4*)&out[(size_t)n * BS * D + (size_t)b * D + otx * 4] = r;
        }
    }
}

// ---------------------------------------------------------------------------
extern "C" void kernel_launch(void* const* d_in, const int* in_sizes, int n_in,
                              void* d_out, int out_size)
{
    const float* q  = (const float*)d_in[0];
    const float* k  = (const float*)d_in[1];
    const float* qw = (const float*)d_in[2];
    const float* kw = (const float*)d_in[3];
    const float* vw = (const float*)d_in[4];
    float* out = (float*)d_out;

    (void)in_sizes; (void)n_in; (void)out_size;

    // Phase 1: projections
    dim3 grid1(2, 32, 96);
    proj_kernel<<<grid1, 256>>>(q, k, qw, kw, vw);

    // Phase 2: per-batch attention (needs >48KB dynamic smem)
    const int smem_bytes = SMEM_FLOATS * (int)sizeof(float);
    cudaFuncSetAttribute(attn_kernel,
                         cudaFuncAttributeMaxDynamicSharedMemorySize,
                         smem_bytes);
    attn_kernel<<<BS, 256, smem_bytes>>>(out);
}

// round 3
// speedup vs baseline: 1.1810x; 1.1810x over previous
#include <cuda_runtime.h>
#include <math.h>
#include <stdint.h>
#include <mma.h>

using namespace nvcuda;

#define BS    4096
#define NSLOT 32
#define D     256

// Scratch (device globals — no runtime allocation allowed). Layout [slot][batch][dim]
__device__ float g_query[(size_t)NSLOT * BS * D];
__device__ float g_keyp [(size_t)NSLOT * BS * D];
__device__ float g_value[(size_t)NSLOT * BS * D];

__device__ __forceinline__ float f2tf32f(float f) {
    uint32_t u;
    asm("cvt.rna.tf32.f32 %0, %1;" : "=r"(u) : "f"(f));
    return __uint_as_float(u);
}

// ---------------------------------------------------------------------------
// Phase 1: 96 GEMMs C[4096,256] = X[4096,256] @ W[256,256] on tensor cores
// (wmma tf32 m16n16k8 — arch-portable HMMA path; tcgen05 PTX is rejected by
//  this harness's .target sm_103).
// grid = (2 n-tiles, 32 m-tiles, 96 gemms), block = 256 (8 warps, 2x4).
// CTA tile 128x128, K-chunk 32, double-buffered smem.
// ---------------------------------------------------------------------------
#define A_LD  36                       // 32 + 4 pad
#define B_LD  132                      // 128 + 4 pad
#define ASZ   (128 * A_LD)             // floats per A stage
#define BSZ   (32 * B_LD)              // floats per B stage
#define STG   (ASZ + BSZ)              // floats per stage
#define PROJ_SMEM_BYTES (2 * STG * (int)sizeof(float))   // ~70.7 KB

__global__ __launch_bounds__(256) void proj_wmma(
    const float* __restrict__ q,
    const float* __restrict__ k,
    const float* __restrict__ qw,
    const float* __restrict__ kw,
    const float* __restrict__ vw)
{
    extern __shared__ float sm[];

    const int tid = threadIdx.x;
    const int wid = tid >> 5;
    const int wm  = wid >> 2;          // 0..1 -> warp row (64 rows)
    const int wn  = wid & 3;           // 0..3 -> warp col (32 cols)
    const int m0  = blockIdx.y * 128;
    const int n0  = blockIdx.x * 128;
    const int gid = blockIdx.z;

    const float* X; const float* W; float* C;
    if (gid < 32)      { X = q + (size_t)gid * BS * D;        W = qw + (size_t)gid * D * D;        C = g_query + (size_t)gid * BS * D; }
    else if (gid < 64) { X = k + (size_t)(gid - 32) * BS * D; W = kw + (size_t)(gid - 32) * D * D; C = g_keyp  + (size_t)(gid - 32) * BS * D; }
    else               { X = k + (size_t)(gid - 64) * BS * D; W = vw + (size_t)(gid - 64) * D * D; C = g_value + (size_t)(gid - 64) * BS * D; }

    // Per-thread staging indices (fixed across chunks)
    const int a_row = tid >> 3;        // 0..31 (+32*p)
    const int a_c4  = (tid & 7) * 4;   // k offset within chunk
    const int b_kk  = tid >> 5;        // 0..7 (+8*p)
    const int b_n4  = (tid & 31) * 4;  // n offset

    float4 ra[4], rb[4];

    // Load chunk c of X/W into registers
    auto load_regs = [&](int c) {
#pragma unroll
        for (int p = 0; p < 4; p++)
            ra[p] = *(const float4*)&X[(size_t)(m0 + a_row + 32 * p) * D + c * 32 + a_c4];
#pragma unroll
        for (int p = 0; p < 4; p++)
            rb[p] = *(const float4*)&W[(size_t)(c * 32 + b_kk + 8 * p) * D + n0 + b_n4];
    };
    // Convert to tf32 and store into smem stage buf
    auto store_smem = [&](int buf) {
        float* a_s = sm + buf * STG;
        float* b_s = a_s + ASZ;
#pragma unroll
        for (int p = 0; p < 4; p++) {
            float4 t;
            t.x = f2tf32f(ra[p].x); t.y = f2tf32f(ra[p].y);
            t.z = f2tf32f(ra[p].z); t.w = f2tf32f(ra[p].w);
            *(float4*)&a_s[(a_row + 32 * p) * A_LD + a_c4] = t;
        }
#pragma unroll
        for (int p = 0; p < 4; p++) {
            float4 t;
            t.x = f2tf32f(rb[p].x); t.y = f2tf32f(rb[p].y);
            t.z = f2tf32f(rb[p].z); t.w = f2tf32f(rb[p].w);
            *(float4*)&b_s[(b_kk + 8 * p) * B_LD + b_n4] = t;
        }
    };

    wmma::fragment<wmma::accumulator, 16, 16, 8, float> cf[4][2];
#pragma unroll
    for (int i = 0; i < 4; i++)
#pragma unroll
        for (int j = 0; j < 2; j++) wmma::fill_fragment(cf[i][j], 0.0f);

    load_regs(0);
    store_smem(0);
    __syncthreads();

    for (int c = 0; c < 8; c++) {
        if (c < 7) load_regs(c + 1);

        const int buf = c & 1;
        const float* a_s = sm + buf * STG;
        const float* b_s = a_s + ASZ;
#pragma unroll
        for (int ks = 0; ks < 4; ks++) {
            wmma::fragment<wmma::matrix_a, 16, 16, 8, wmma::precision::tf32, wmma::row_major> af[4];
            wmma::fragment<wmma::matrix_b, 16, 16, 8, wmma::precision::tf32, wmma::row_major> bf[2];
#pragma unroll
            for (int i = 0; i < 4; i++)
                wmma::load_matrix_sync(af[i], a_s + (wm * 64 + 16 * i) * A_LD + ks * 8, A_LD);
#pragma unroll
            for (int j = 0; j < 2; j++)
                wmma::load_matrix_sync(bf[j], b_s + (ks * 8) * B_LD + wn * 32 + 16 * j, B_LD);
#pragma unroll
            for (int i = 0; i < 4; i++)
#pragma unroll
                for (int j = 0; j < 2; j++)
                    wmma::mma_sync(cf[i][j], af[i], bf[j], cf[i][j]);
        }

        if (c < 7) store_smem((c + 1) & 1);
        __syncthreads();
    }

    // Epilogue: straight to global
#pragma unroll
    for (int i = 0; i < 4; i++)
#pragma unroll
        for (int j = 0; j < 2; j++)
            wmma::store_matrix_sync(
                &C[(size_t)(m0 + wm * 64 + 16 * i) * D + n0 + wn * 32 + 16 * j],
                cf[i][j], D, wmma::mem_row_major);
}

// ---------------------------------------------------------------------------
// Phase 2: per-batch attention. grid = 4096, block = 256. (unchanged)
// ---------------------------------------------------------------------------
#define SK_STRIDE 257
#define SMEM_FLOATS (32*256 + 32*SK_STRIDE + 32*256 + 32*32)

__global__ __launch_bounds__(256) void attn_kernel(float* __restrict__ out)
{
    extern __shared__ float smf[];
    float* sq = smf;
    float* sk = sq + 32 * 256;
    float* sv = sk + 32 * SK_STRIDE;
    float* lg = sv + 32 * 256;

    const int b   = blockIdx.x;
    const int tid = threadIdx.x;

    for (int i = tid; i < 32 * 64; i += 256) {
        const int n  = i >> 6;
        const int a4 = (i & 63) * 4;
        const size_t g = (size_t)n * BS * D + (size_t)b * D + a4;
        const float4 vq = *(const float4*)&g_query[g];
        *(float4*)&sq[n * 256 + a4] = vq;
        const float4 vv = *(const float4*)&g_value[g];
        *(float4*)&sv[n * 256 + a4] = vv;
        const float4 vk = *(const float4*)&g_keyp[g];
        sk[n * SK_STRIDE + a4 + 0] = vk.x;
        sk[n * SK_STRIDE + a4 + 1] = vk.y;
        sk[n * SK_STRIDE + a4 + 2] = vk.z;
        sk[n * SK_STRIDE + a4 + 3] = vk.w;
    }
    __syncthreads();

    {
        const int ltx = tid & 15;
        const int lty = tid >> 4;
        const int n0 = lty * 2;
        const int m0 = ltx * 2;
        float c00 = 0.f, c01 = 0.f, c10 = 0.f, c11 = 0.f;
        const float* q0p = &sq[n0 * 256];
        const float* q1p = &sq[(n0 + 1) * 256];
        const float* k0p = &sk[m0 * SK_STRIDE];
        const float* k1p = &sk[(m0 + 1) * SK_STRIDE];
#pragma unroll 8
        for (int a = 0; a < 256; a++) {
            const float q0 = q0p[a];
            const float q1 = q1p[a];
            const float k0 = k0p[a];
            const float k1 = k1p[a];
            c00 = fmaf(q0, k0, c00);
            c01 = fmaf(q0, k1, c01);
            c10 = fmaf(q1, k0, c10);
            c11 = fmaf(q1, k1, c11);
        }
        lg[n0 * 32 + m0]           = c00;
        lg[n0 * 32 + m0 + 1]       = c01;
        lg[(n0 + 1) * 32 + m0]     = c10;
        lg[(n0 + 1) * 32 + m0 + 1] = c11;
    }
    __syncthreads();

    if (tid < 32) {
        float mx = -1e30f;
#pragma unroll
        for (int m = 0; m < 32; m++) mx = fmaxf(mx, lg[tid * 32 + m]);
        float s = 0.0f;
        float e[32];
#pragma unroll
        for (int m = 0; m < 32; m++) {
            e[m] = expf((lg[tid * 32 + m] - mx) * (1.0f / 16.0f));
            s += e[m];
        }
        const float inv = 1.0f / s;
#pragma unroll
        for (int m = 0; m < 32; m++) lg[tid * 32 + m] = e[m] * inv;
    }
    __syncthreads();

    {
        const int otx = tid & 63;
        const int oty = tid >> 6;
        float acc[8][4];
#pragma unroll
        for (int j = 0; j < 8; j++)
#pragma unroll
            for (int c = 0; c < 4; c++) acc[j][c] = 0.0f;

#pragma unroll 4
        for (int m = 0; m < 32; m++) {
            const float4 v = *(const float4*)&sv[m * 256 + otx * 4];
#pragma unroll
            for (int j = 0; j < 8; j++) {
                const float p = lg[(oty + j * 4) * 32 + m];
                acc[j][0] = fmaf(p, v.x, acc[j][0]);
                acc[j][1] = fmaf(p, v.y, acc[j][1]);
                acc[j][2] = fmaf(p, v.z, acc[j][2]);
                acc[j][3] = fmaf(p, v.w, acc[j][3]);
            }
        }
#pragma unroll
        for (int j = 0; j < 8; j++) {
            const int n = oty + j * 4;
            float4 r;
            r.x = acc[j][0]; r.y = acc[j][1]; r.z = acc[j][2]; r.w = acc[j][3];
            *(float4*)&out[(size_t)n * BS * D + (size_t)b * D + otx * 4] = r;
        }
    }
}

// ---------------------------------------------------------------------------
extern "C" void kernel_launch(void* const* d_in, const int* in_sizes, int n_in,
                              void* d_out, int out_size)
{
    const float* q  = (const float*)d_in[0];
    const float* k  = (const float*)d_in[1];
    const float* qw = (const float*)d_in[2];
    const float* kw = (const float*)d_in[3];
    const float* vw = (const float*)d_in[4];
    float* out = (float*)d_out;

    (void)in_sizes; (void)n_in; (void)out_size;

    // Phase 1: projections on tensor cores (wmma tf32)
    cudaFuncSetAttribute(proj_wmma, cudaFuncAttributeMaxDynamicSharedMemorySize, PROJ_SMEM_BYTES);
    dim3 grid1(2, 32, 96);
    proj_wmma<<<grid1, 256, PROJ_SMEM_BYTES>>>(q, k, qw, kw, vw);

    // Phase 2: per-batch attention
    const int smem_bytes = SMEM_FLOATS * (int)sizeof(float);
    cudaFuncSetAttribute(attn_kernel, cudaFuncAttributeMaxDynamicSharedMemorySize, smem_bytes);
    attn_kernel<<<BS, 256, smem_bytes>>>(out);
}

// round 4
// speedup vs baseline: 2.9503x; 2.4982x over previous
#include <cuda_runtime.h>
#include <cuda_fp16.h>
#include <math.h>
#include <stdint.h>
#include <mma.h>

using namespace nvcuda;

#define BS    4096
#define NSLOT 32
#define D     256

// Scratch (device globals). Layout [slot][batch][dim]
__device__ float g_query[(size_t)NSLOT * BS * D];
__device__ float g_keyp [(size_t)NSLOT * BS * D];
__device__ float g_value[(size_t)NSLOT * BS * D];

// ---------------------------------------------------------------------------
// Phase 1: 96 GEMMs C[4096,256] = X[4096,256] @ W[256,256], fp16 HMMA
// (wmma m16n16k16 half->float; tf32 legacy HMMA measured ~55TF/s, fp16 is 2x
//  FLOP per issue slot). grid = (2, 32, 96), block = 256 (8 warps, 2x4),
// CTA tile 128x128, K-chunk 32, double-buffered half smem, 2 CTAs/SM.
// ---------------------------------------------------------------------------
#define A_LD  40                         // halfs: 32 + 8 pad
#define B_LD  136                        // halfs: 128 + 8 pad
#define ASZ   (128 * A_LD)               // halfs per A stage
#define BSZ   (32 * B_LD)                // halfs per B stage
#define STG   (ASZ + BSZ)                // halfs per stage
#define PROJ_SMEM_BYTES (2 * STG * (int)sizeof(__half))   // ~37.9 KB

__global__ __launch_bounds__(256, 2) void proj_wmma(
    const float* __restrict__ q,
    const float* __restrict__ k,
    const float* __restrict__ qw,
    const float* __restrict__ kw,
    const float* __restrict__ vw)
{
    extern __shared__ __align__(16) __half smh[];

    const int tid = threadIdx.x;
    const int wid = tid >> 5;
    const int wm  = wid >> 2;            // 0..1 -> warp row (64 rows)
    const int wn  = wid & 3;             // 0..3 -> warp col (32 cols)
    const int m0  = blockIdx.y * 128;
    const int n0  = blockIdx.x * 128;
    const int gid = blockIdx.z;

    const float* X; const float* W; float* C;
    if (gid < 32)      { X = q + (size_t)gid * BS * D;        W = qw + (size_t)gid * D * D;        C = g_query + (size_t)gid * BS * D; }
    else if (gid < 64) { X = k + (size_t)(gid - 32) * BS * D; W = kw + (size_t)(gid - 32) * D * D; C = g_keyp  + (size_t)(gid - 32) * BS * D; }
    else               { X = k + (size_t)(gid - 64) * BS * D; W = vw + (size_t)(gid - 64) * D * D; C = g_value + (size_t)(gid - 64) * BS * D; }

    // Staging indices
    const int a_row = tid >> 3;          // 0..31 (+32*p)
    const int a_c4  = (tid & 7) * 4;     // k offset in chunk
    const int b_kk  = tid >> 5;          // 0..7 (+8*p)
    const int b_n4  = (tid & 31) * 4;    // n offset

    float4 ra[4], rb[4];

    auto load_regs = [&](int c) {
#pragma unroll
        for (int p = 0; p < 4; p++)
            ra[p] = *(const float4*)&X[(size_t)(m0 + a_row + 32 * p) * D + c * 32 + a_c4];
#pragma unroll
        for (int p = 0; p < 4; p++)
            rb[p] = *(const float4*)&W[(size_t)(c * 32 + b_kk + 8 * p) * D + n0 + b_n4];
    };
    auto store_smem = [&](int buf) {
        __half* a_s = smh + buf * STG;
        __half* b_s = a_s + ASZ;
#pragma unroll
        for (int p = 0; p < 4; p++) {
            __half2 h0 = __floats2half2_rn(ra[p].x, ra[p].y);
            __half2 h1 = __floats2half2_rn(ra[p].z, ra[p].w);
            *(__half2*)&a_s[(a_row + 32 * p) * A_LD + a_c4]     = h0;
            *(__half2*)&a_s[(a_row + 32 * p) * A_LD + a_c4 + 2] = h1;
        }
#pragma unroll
        for (int p = 0; p < 4; p++) {
            __half2 h0 = __floats2half2_rn(rb[p].x, rb[p].y);
            __half2 h1 = __floats2half2_rn(rb[p].z, rb[p].w);
            *(__half2*)&b_s[(b_kk + 8 * p) * B_LD + b_n4]     = h0;
            *(__half2*)&b_s[(b_kk + 8 * p) * B_LD + b_n4 + 2] = h1;
        }
    };

    wmma::fragment<wmma::accumulator, 16, 16, 16, float> cf[4][2];
#pragma unroll
    for (int i = 0; i < 4; i++)
#pragma unroll
        for (int j = 0; j < 2; j++) wmma::fill_fragment(cf[i][j], 0.0f);

    load_regs(0);
    store_smem(0);
    __syncthreads();

    for (int c = 0; c < 8; c++) {
        if (c < 7) load_regs(c + 1);

        const int buf = c & 1;
        const __half* a_s = smh + buf * STG;
        const __half* b_s = a_s + ASZ;
#pragma unroll
        for (int ks = 0; ks < 2; ks++) {          // two k16 slabs per 32-chunk
            wmma::fragment<wmma::matrix_a, 16, 16, 16, __half, wmma::row_major> af[4];
            wmma::fragment<wmma::matrix_b, 16, 16, 16, __half, wmma::row_major> bf[2];
#pragma unroll
            for (int i = 0; i < 4; i++)
                wmma::load_matrix_sync(af[i], a_s + (wm * 64 + 16 * i) * A_LD + ks * 16, A_LD);
#pragma unroll
            for (int j = 0; j < 2; j++)
                wmma::load_matrix_sync(bf[j], b_s + (ks * 16) * B_LD + wn * 32 + 16 * j, B_LD);
#pragma unroll
            for (int i = 0; i < 4; i++)
#pragma unroll
                for (int j = 0; j < 2; j++)
                    wmma::mma_sync(cf[i][j], af[i], bf[j], cf[i][j]);
        }

        if (c < 7) store_smem((c + 1) & 1);
        __syncthreads();
    }

#pragma unroll
    for (int i = 0; i < 4; i++)
#pragma unroll
        for (int j = 0; j < 2; j++)
            wmma::store_matrix_sync(
                &C[(size_t)(m0 + wm * 64 + 16 * i) * D + n0 + wn * 32 + 16 * j],
                cf[i][j], D, wmma::mem_row_major);
}

// ---------------------------------------------------------------------------
// Phase 2: per-batch attention. grid = 4096, block = 256. (unchanged)
// ---------------------------------------------------------------------------
#define SK_STRIDE 257
#define SMEM_FLOATS (32*256 + 32*SK_STRIDE + 32*256 + 32*32)

__global__ __launch_bounds__(256) void attn_kernel(float* __restrict__ out)
{
    extern __shared__ float smf[];
    float* sq = smf;
    float* sk = sq + 32 * 256;
    float* sv = sk + 32 * SK_STRIDE;
    float* lg = sv + 32 * 256;

    const int b   = blockIdx.x;
    const int tid = threadIdx.x;

    for (int i = tid; i < 32 * 64; i += 256) {
        const int n  = i >> 6;
        const int a4 = (i & 63) * 4;
        const size_t g = (size_t)n * BS * D + (size_t)b * D + a4;
        const float4 vq = *(const float4*)&g_query[g];
        *(float4*)&sq[n * 256 + a4] = vq;
        const float4 vv = *(const float4*)&g_value[g];
        *(float4*)&sv[n * 256 + a4] = vv;
        const float4 vk = *(const float4*)&g_keyp[g];
        sk[n * SK_STRIDE + a4 + 0] = vk.x;
        sk[n * SK_STRIDE + a4 + 1] = vk.y;
        sk[n * SK_STRIDE + a4 + 2] = vk.z;
        sk[n * SK_STRIDE + a4 + 3] = vk.w;
    }
    __syncthreads();

    {
        const int ltx = tid & 15;
        const int lty = tid >> 4;
        const int n0 = lty * 2;
        const int m0 = ltx * 2;
        float c00 = 0.f, c01 = 0.f, c10 = 0.f, c11 = 0.f;
        const float* q0p = &sq[n0 * 256];
        const float* q1p = &sq[(n0 + 1) * 256];
        const float* k0p = &sk[m0 * SK_STRIDE];
        const float* k1p = &sk[(m0 + 1) * SK_STRIDE];
#pragma unroll 8
        for (int a = 0; a < 256; a++) {
            const float q0 = q0p[a];
            const float q1 = q1p[a];
            const float k0 = k0p[a];
            const float k1 = k1p[a];
            c00 = fmaf(q0, k0, c00);
            c01 = fmaf(q0, k1, c01);
            c10 = fmaf(q1, k0, c10);
            c11 = fmaf(q1, k1, c11);
        }
        lg[n0 * 32 + m0]           = c00;
        lg[n0 * 32 + m0 + 1]       = c01;
        lg[(n0 + 1) * 32 + m0]     = c10;
        lg[(n0 + 1) * 32 + m0 + 1] = c11;
    }
    __syncthreads();

    if (tid < 32) {
        float mx = -1e30f;
#pragma unroll
        for (int m = 0; m < 32; m++) mx = fmaxf(mx, lg[tid * 32 + m]);
        float s = 0.0f;
        float e[32];
#pragma unroll
        for (int m = 0; m < 32; m++) {
            e[m] = expf((lg[tid * 32 + m] - mx) * (1.0f / 16.0f));
            s += e[m];
        }
        const float inv = 1.0f / s;
#pragma unroll
        for (int m = 0; m < 32; m++) lg[tid * 32 + m] = e[m] * inv;
    }
    __syncthreads();

    {
        const int otx = tid & 63;
        const int oty = tid >> 6;
        float acc[8][4];
#pragma unroll
        for (int j = 0; j < 8; j++)
#pragma unroll
            for (int c = 0; c < 4; c++) acc[j][c] = 0.0f;

#pragma unroll 4
        for (int m = 0; m < 32; m++) {
            const float4 v = *(const float4*)&sv[m * 256 + otx * 4];
#pragma unroll
            for (int j = 0; j < 8; j++) {
                const float p = lg[(oty + j * 4) * 32 + m];
                acc[j][0] = fmaf(p, v.x, acc[j][0]);
                acc[j][1] = fmaf(p, v.y, acc[j][1]);
                acc[j][2] = fmaf(p, v.z, acc[j][2]);
                acc[j][3] = fmaf(p, v.w, acc[j][3]);
            }
        }
#pragma unroll
        for (int j = 0; j < 8; j++) {
            const int n = oty + j * 4;
            float4 r;
            r.x = acc[j][0]; r.y = acc[j][1]; r.z = acc[j][2]; r.w = acc[j][3];
            *(float4*)&out[(size_t)n * BS * D + (size_t)b * D + otx * 4] = r;
        }
    }
}

// ---------------------------------------------------------------------------
extern "C" void kernel_launch(void* const* d_in, const int* in_sizes, int n_in,
                              void* d_out, int out_size)
{
    const float* q  = (const float*)d_in[0];
    const float* k  = (const float*)d_in[1];
    const float* qw = (const float*)d_in[2];
    const float* kw = (const float*)d_in[3];
    const float* vw = (const float*)d_in[4];
    float* out = (float*)d_out;

    (void)in_sizes; (void)n_in; (void)out_size;

    cudaFuncSetAttribute(proj_wmma, cudaFuncAttributeMaxDynamicSharedMemorySize, PROJ_SMEM_BYTES);
    dim3 grid1(2, 32, 96);
    proj_wmma<<<grid1, 256, PROJ_SMEM_BYTES>>>(q, k, qw, kw, vw);

    const int smem_bytes = SMEM_FLOATS * (int)sizeof(float);
    cudaFuncSetAttribute(attn_kernel, cudaFuncAttributeMaxDynamicSharedMemorySize, smem_bytes);
    attn_kernel<<<BS, 256, smem_bytes>>>(out);
}

// round 5
// speedup vs baseline: 4.1400x; 1.4032x over previous
#include <cuda_runtime.h>
#include <cuda_fp16.h>
#include <math.h>
#include <stdint.h>
#include <mma.h>

using namespace nvcuda;

#define BS    4096
#define NSLOT 32
#define D     256

// Scratch (device globals), fp16. Layout [slot][batch][dim]
__device__ __half g_query[(size_t)NSLOT * BS * D];
__device__ __half g_keyp [(size_t)NSLOT * BS * D];
__device__ __half g_value[(size_t)NSLOT * BS * D];

// ---------------------------------------------------------------------------
// Phase 1: 96 GEMMs C[4096,256] = X[4096,256] @ W[256,256], fp16 HMMA.
// grid (2,32,96), block 256 (8 warps 2x4), CTA tile 128x128, K-chunk 32,
// double-buffered half smem, 2 CTAs/SM. Epilogue converts to fp16 scratch.
// ---------------------------------------------------------------------------
#define A_LD  40
#define B_LD  136
#define ASZ   (128 * A_LD)
#define BSZ   (32 * B_LD)
#define STG   (ASZ + BSZ)
#define PROJ_SMEM_BYTES (2 * STG * (int)sizeof(__half))   // ~37.9 KB

__global__ __launch_bounds__(256, 2) void proj_wmma(
    const float* __restrict__ q,
    const float* __restrict__ k,
    const float* __restrict__ qw,
    const float* __restrict__ kw,
    const float* __restrict__ vw)
{
    extern __shared__ __align__(16) __half smh[];

    const int tid = threadIdx.x;
    const int wid = tid >> 5;
    const int lane = tid & 31;
    const int wm  = wid >> 2;
    const int wn  = wid & 3;
    const int m0  = blockIdx.y * 128;
    const int n0  = blockIdx.x * 128;
    const int gid = blockIdx.z;

    const float* X; const float* W; __half* C;
    if (gid < 32)      { X = q + (size_t)gid * BS * D;        W = qw + (size_t)gid * D * D;        C = g_query + (size_t)gid * BS * D; }
    else if (gid < 64) { X = k + (size_t)(gid - 32) * BS * D; W = kw + (size_t)(gid - 32) * D * D; C = g_keyp  + (size_t)(gid - 32) * BS * D; }
    else               { X = k + (size_t)(gid - 64) * BS * D; W = vw + (size_t)(gid - 64) * D * D; C = g_value + (size_t)(gid - 64) * BS * D; }

    const int a_row = tid >> 3;
    const int a_c4  = (tid & 7) * 4;
    const int b_kk  = tid >> 5;
    const int b_n4  = (tid & 31) * 4;

    float4 ra[4], rb[4];

    auto load_regs = [&](int c) {
#pragma unroll
        for (int p = 0; p < 4; p++)
            ra[p] = *(const float4*)&X[(size_t)(m0 + a_row + 32 * p) * D + c * 32 + a_c4];
#pragma unroll
        for (int p = 0; p < 4; p++)
            rb[p] = *(const float4*)&W[(size_t)(c * 32 + b_kk + 8 * p) * D + n0 + b_n4];
    };
    auto store_smem = [&](int buf) {
        __half* a_s = smh + buf * STG;
        __half* b_s = a_s + ASZ;
#pragma unroll
        for (int p = 0; p < 4; p++) {
            __half2 h0 = __floats2half2_rn(ra[p].x, ra[p].y);
            __half2 h1 = __floats2half2_rn(ra[p].z, ra[p].w);
            *(__half2*)&a_s[(a_row + 32 * p) * A_LD + a_c4]     = h0;
            *(__half2*)&a_s[(a_row + 32 * p) * A_LD + a_c4 + 2] = h1;
        }
#pragma unroll
        for (int p = 0; p < 4; p++) {
            __half2 h0 = __floats2half2_rn(rb[p].x, rb[p].y);
            __half2 h1 = __floats2half2_rn(rb[p].z, rb[p].w);
            *(__half2*)&b_s[(b_kk + 8 * p) * B_LD + b_n4]     = h0;
            *(__half2*)&b_s[(b_kk + 8 * p) * B_LD + b_n4 + 2] = h1;
        }
    };

    wmma::fragment<wmma::accumulator, 16, 16, 16, float> cf[4][2];
#pragma unroll
    for (int i = 0; i < 4; i++)
#pragma unroll
        for (int j = 0; j < 2; j++) wmma::fill_fragment(cf[i][j], 0.0f);

    load_regs(0);
    store_smem(0);
    __syncthreads();

    for (int c = 0; c < 8; c++) {
        if (c < 7) load_regs(c + 1);

        const int buf = c & 1;
        const __half* a_s = smh + buf * STG;
        const __half* b_s = a_s + ASZ;
#pragma unroll
        for (int ks = 0; ks < 2; ks++) {
            wmma::fragment<wmma::matrix_a, 16, 16, 16, __half, wmma::row_major> af[4];
            wmma::fragment<wmma::matrix_b, 16, 16, 16, __half, wmma::row_major> bf[2];
#pragma unroll
            for (int i = 0; i < 4; i++)
                wmma::load_matrix_sync(af[i], a_s + (wm * 64 + 16 * i) * A_LD + ks * 16, A_LD);
#pragma unroll
            for (int j = 0; j < 2; j++)
                wmma::load_matrix_sync(bf[j], b_s + (ks * 16) * B_LD + wn * 32 + 16 * j, B_LD);
#pragma unroll
            for (int i = 0; i < 4; i++)
#pragma unroll
                for (int j = 0; j < 2; j++)
                    wmma::mma_sync(cf[i][j], af[i], bf[j], cf[i][j]);
        }

        if (c < 7) store_smem((c + 1) & 1);
        __syncthreads();
    }

    // Epilogue: stage fp32 tile -> convert -> fp16 gmem (per-warp 16x20 buffer)
    float* stg = reinterpret_cast<float*>(smh) + wid * (16 * 20);
    const int er = lane >> 1;
    const int ec = (lane & 1) * 8;
#pragma unroll
    for (int i = 0; i < 4; i++) {
#pragma unroll
        for (int j = 0; j < 2; j++) {
            wmma::store_matrix_sync(stg, cf[i][j], 20, wmma::mem_row_major);
            __syncwarp();
            __half2 h[4];
#pragma unroll
            for (int t = 0; t < 4; t++)
                h[t] = __floats2half2_rn(stg[er * 20 + ec + 2 * t], stg[er * 20 + ec + 2 * t + 1]);
            *(uint4*)&C[(size_t)(m0 + wm * 64 + 16 * i + er) * D + n0 + wn * 32 + 16 * j + ec] =
                *(uint4*)&h[0];
            __syncwarp();
        }
    }
}

// ---------------------------------------------------------------------------
// Phase 2: per-batch attention on tensor cores. grid 4096, block 256 (8 warps).
// smem: qh/kh/vh [32][264] half, lg [2][32][36] fp32 (K-split partials),
//       ph [32][40] half.
// ---------------------------------------------------------------------------
#define QK_LD 264
#define LG_LD 36
#define P_LD  40
#define ATTN_SMEM_BYTES ((3 * 32 * QK_LD) * 2 + (2 * 32 * LG_LD) * 4 + (32 * P_LD) * 2)

__global__ __launch_bounds__(256) void attn_tc(float* __restrict__ out)
{
    extern __shared__ __align__(16) __half smem_h[];
    __half* qh = smem_h;                       // 32*264
    __half* kh = qh + 32 * QK_LD;              // 32*264
    __half* vh = kh + 32 * QK_LD;              // 32*264
    float*  lg = (float*)(vh + 32 * QK_LD);    // 2*32*36 fp32
    __half* ph = (__half*)(lg + 2 * 32 * LG_LD); // 32*40

    const int b    = blockIdx.x;
    const int tid  = threadIdx.x;
    const int wid  = tid >> 5;

    // Stage q/k/v (half): 1024 uint4 chunks per tensor? -> 32*256/8 = 1024; 4/thread
#pragma unroll
    for (int p = 0; p < 4; p++) {
        const int idx = p * 256 + tid;
        const int n  = idx >> 5;
        const int a8 = (idx & 31) * 8;
        const size_t g = (size_t)n * BS * D + (size_t)b * D + a8;
        *(uint4*)&qh[n * QK_LD + a8] = *(const uint4*)&g_query[g];
        *(uint4*)&kh[n * QK_LD + a8] = *(const uint4*)&g_keyp[g];
        *(uint4*)&vh[n * QK_LD + a8] = *(const uint4*)&g_value[g];
    }
    __syncthreads();

    // Logits: lg_part[khalf][n][m] = sum_{a in half} qh[n][a] * kh[m][a]
    {
        const int khalf = wid >> 2;
        const int nt = (wid >> 1) & 1;
        const int mt = wid & 1;
        wmma::fragment<wmma::accumulator, 16, 16, 16, float> acc;
        wmma::fill_fragment(acc, 0.0f);
#pragma unroll
        for (int ks = 0; ks < 8; ks++) {
            const int k0 = khalf * 128 + ks * 16;
            wmma::fragment<wmma::matrix_a, 16, 16, 16, __half, wmma::row_major> af;
            wmma::fragment<wmma::matrix_b, 16, 16, 16, __half, wmma::col_major> bf;
            wmma::load_matrix_sync(af, qh + (nt * 16) * QK_LD + k0, QK_LD);
            wmma::load_matrix_sync(bf, kh + (mt * 16) * QK_LD + k0, QK_LD);
            wmma::mma_sync(acc, af, bf, acc);
        }
        wmma::store_matrix_sync(lg + khalf * 32 * LG_LD + (nt * 16) * LG_LD + mt * 16,
                                acc, LG_LD, wmma::mem_row_major);
    }
    __syncthreads();

    // Softmax (fp32), write P as half
    if (tid < 32) {
        const float* l0 = lg + tid * LG_LD;
        const float* l1 = lg + 32 * LG_LD + tid * LG_LD;
        float x[32];
        float mx = -1e30f;
#pragma unroll
        for (int m = 0; m < 32; m++) {
            x[m] = l0[m] + l1[m];
            mx = fmaxf(mx, x[m]);
        }
        float s = 0.0f;
#pragma unroll
        for (int m = 0; m < 32; m++) {
            x[m] = expf((x[m] - mx) * (1.0f / 16.0f));
            s += x[m];
        }
        const float inv = 1.0f / s;
#pragma unroll
        for (int m = 0; m < 32; m += 2)
            *(__half2*)&ph[tid * P_LD + m] = __floats2half2_rn(x[m] * inv, x[m + 1] * inv);
    }
    __syncthreads();

    // Output: out[n][o] = sum_m P[n][m] * vh[m][o]; warp: mt2 = wid>>2, o-chunk = wid&3
    {
        const int mt2 = wid >> 2;
        const int oc  = wid & 3;
        wmma::fragment<wmma::accumulator, 16, 16, 16, float> acc[4];
#pragma unroll
        for (int j = 0; j < 4; j++) wmma::fill_fragment(acc[j], 0.0f);
#pragma unroll
        for (int ks = 0; ks < 2; ks++) {
            wmma::fragment<wmma::matrix_a, 16, 16, 16, __half, wmma::row_major> af;
            wmma::load_matrix_sync(af, ph + (mt2 * 16) * P_LD + ks * 16, P_LD);
#pragma unroll
            for (int j = 0; j < 4; j++) {
                wmma::fragment<wmma::matrix_b, 16, 16, 16, __half, wmma::row_major> bf;
                wmma::load_matrix_sync(bf, vh + (ks * 16) * QK_LD + oc * 64 + j * 16, QK_LD);
                wmma::mma_sync(acc[j], af, bf, acc[j]);
            }
        }
#pragma unroll
        for (int j = 0; j < 4; j++) {
            float* dst = out + (size_t)(mt2 * 16) * BS * D + (size_t)b * D + oc * 64 + j * 16;
            wmma::store_matrix_sync(dst, acc[j], (unsigned)(BS * D), wmma::mem_row_major);
        }
    }
}

// ---------------------------------------------------------------------------
extern "C" void kernel_launch(void* const* d_in, const int* in_sizes, int n_in,
                              void* d_out, int out_size)
{
    const float* q  = (const float*)d_in[0];
    const float* k  = (const float*)d_in[1];
    const float* qw = (const float*)d_in[2];
    const float* kw = (const float*)d_in[3];
    const float* vw = (const float*)d_in[4];
    float* out = (float*)d_out;

    (void)in_sizes; (void)n_in; (void)out_size;

    cudaFuncSetAttribute(proj_wmma, cudaFuncAttributeMaxDynamicSharedMemorySize, PROJ_SMEM_BYTES);
    dim3 grid1(2, 32, 96);
    proj_wmma<<<grid1, 256, PROJ_SMEM_BYTES>>>(q, k, qw, kw, vw);

    cudaFuncSetAttribute(attn_tc, cudaFuncAttributeMaxDynamicSharedMemorySize, ATTN_SMEM_BYTES);
    attn_tc<<<BS, 256, ATTN_SMEM_BYTES>>>(out);
}